// round 6
// baseline (speedup 1.0000x reference)
#include <cuda_runtime.h>
#include <math.h>

#define S   20
#define SS  400
#define J   15          // precomputed powers / Taylor degree
#define THETA 2.0f

// ---- device scratch ----
__device__ float g_Qpow[64 * J * SS];   // per (m,k): Q^1..Q^J row-major
__device__ float g_an[64];              // per (m,k): ||Q||_inf

__device__ __forceinline__ float softplusf(float x) {
    return fmaxf(x, 0.0f) + log1pf(expf(-fabsf(x)));
}
__device__ __forceinline__ float wred_max(float v) {
#pragma unroll
    for (int o = 16; o > 0; o >>= 1) v = fmaxf(v, __shfl_xor_sync(0xffffffffu, v, o));
    return v;
}
__device__ __forceinline__ float wred_sum(float v) {
#pragma unroll
    for (int o = 16; o > 0; o >>= 1) v += __shfl_xor_sync(0xffffffffu, v, o);
    return v;
}

__device__ __forceinline__ float4 identity4(int n) {
    float4 id = make_float4(0.f, 0.f, 0.f, 0.f);
    const int e = 4 * n;
    if ((e+0) / S == (e+0) % S) id.x = 1.0f;
    if ((e+1) / S == (e+1) % S) id.y = 1.0f;
    if ((e+2) / S == (e+2) % S) id.z = 1.0f;
    if ((e+3) / S == (e+3) % S) id.w = 1.0f;
    return id;
}

// c[i] = sum_t M[t*20+i] * a[t]   (M col-major, f4-aligned)
__device__ __forceinline__ void matvec_cols(const float* __restrict__ M,
                                            const float* __restrict__ a,
                                            float* __restrict__ c) {
#pragma unroll
    for (int i = 0; i < S; i++) c[i] = 0.0f;
    const float4* M4 = reinterpret_cast<const float4*>(M);
#pragma unroll
    for (int t = 0; t < S; t++) {
        const float av = a[t];
#pragma unroll
        for (int q = 0; q < 5; q++) {
            float4 v = M4[t * 5 + q];
            c[4*q+0] = fmaf(v.x, av, c[4*q+0]);
            c[4*q+1] = fmaf(v.y, av, c[4*q+1]);
            c[4*q+2] = fmaf(v.z, av, c[4*q+2]);
            c[4*q+3] = fmaf(v.w, av, c[4*q+3]);
        }
    }
}

// ---------------- setup: one block per (m,k); warp w computes Q^{w+1} ----------------
__global__ void __launch_bounds__(32 * J)
setup_kernel(const float* __restrict__ exch, const float* __restrict__ eq)
{
    __shared__ __align__(16) float sQ[SS];
    __shared__ __align__(16) float slot[J][SS];
    __shared__ float sp[S];

    const int mat  = blockIdx.x;
    const int wid  = threadIdx.x >> 5;
    const int lane = threadIdx.x & 31;

    if (wid == 0) {
        const float* Ek = exch + (size_t)mat * SS;
        const float* ek = eq   + (size_t)mat * S;
        float x  = (lane < S) ? ek[lane] : -3.0e38f;
        float mx = wred_max(x);
        float ex = (lane < S) ? expf(x - mx) : 0.0f;
        float pl = ex / wred_sum(ex);
        if (lane < S) sp[lane] = pl;
        __syncwarp();
        float qrow[S];
        float diag = 0.0f;
        if (lane < S) {
#pragma unroll
            for (int j = 0; j < S; j++) {
                float r = (j == lane) ? 0.0f
                        : softplusf(0.5f * (Ek[lane * S + j] + Ek[j * S + lane]));
                float q = r * sp[j];
                qrow[j] = q;
                diag += q;
            }
            qrow[lane] = -diag;
        }
        float mue = wred_sum((lane < S) ? pl * diag : 0.0f);
        const float inv = 1.0f / fmaxf(mue, 1e-16f);
        if (lane < S) {
#pragma unroll
            for (int j = 0; j < S; j++) sQ[j * S + lane] = qrow[j] * inv;
        }
        const float an = wred_max((lane < S) ? 2.0f * diag * inv : 0.0f);
        if (lane == 0) g_an[mat] = an;
    }
    __syncthreads();

    const int p   = wid + 1;
    const int col = (lane < S) ? lane : 0;
    float a[S], c[S];
#pragma unroll
    for (int i = 0; i < S; i++) a[i] = sQ[col * S + i];

    const int hb = 31 - __clz(p);
    for (int bit = hb - 1; bit >= 0; bit--) {
        __syncwarp();
        if (lane < S) {
#pragma unroll
            for (int i = 0; i < S; i++) slot[wid][col * S + i] = a[i];
        }
        __syncwarp();
        matvec_cols(&slot[wid][0], a, c);
#pragma unroll
        for (int i = 0; i < S; i++) a[i] = c[i];
        if ((p >> bit) & 1) {
            matvec_cols(sQ, a, c);
#pragma unroll
            for (int i = 0; i < S; i++) a[i] = c[i];
        }
    }
    if (lane < S) {
        float* dst = g_Qpow + ((size_t)mat * J + (p - 1)) * SS;
#pragma unroll
        for (int i = 0; i < S; i++) dst[i * S + col] = a[i];
    }
}

// ---------------- main ----------------
// smem P layout: interleaved by matrix row: sP[s][k][20] (float4-aligned since K*20 % 4 == 0).
template <int K>
__global__ void __launch_bounds__(256, 4)
main_kernel(const int*   __restrict__ seq,    // (m,b,L)
            const int*   __restrict__ ridx,   // (m,b)
            const float* __restrict__ tauk,   // (m,num_rates)
            float*       __restrict__ out,    // (m,b,L,K,20)
            int b, int L, int nr)
{
    constexpr int NK4   = K * 5;                 // float4 per l
    constexpr int SROW  = K * S;                 // floats per interleaved row
    constexpr int SPLIT = (K <= 2) ? 2 : 1;      // warps per matrix in lincomb
    constexpr int LW    = K * SPLIT;             // lincomb warps
    constexpr int CH    = (SPLIT == 2) ? 2 : 4;  // float4 chunks per lane
    constexpr int LPW   = 32 / NK4;              // l's handled per warp-pass
    constexpr int ACT   = LPW * NK4;             // active lanes in gather

    extern __shared__ float smem[];
    float* sP   = smem;                          // [S][K][S] interleaved rows
    int*   sseq = (int*)(smem + S * SROW);       // [L]

    const int pb   = blockIdx.x;
    const int tid  = threadIdx.x;
    const int wid  = tid >> 5;
    const int lane = tid & 31;

    int   kk = 0, sq_cnt = 0;

    if (wid < LW) {
        kk = wid % K;
        const int half = wid / K;
        const int mi   = pb / b;
        const int mat  = mi * K + kk;

        const float tau = softplusf(tauk[mi * nr + ridx[pb]]);
        const float an  = g_an[mat];
        float f = tau;
        while (f * an > THETA && sq_cnt < 40) { f *= 0.5f; sq_cnt++; }

        const float4* T4 = reinterpret_cast<const float4*>(g_Qpow + (size_t)mat * J * SS);
        float4* sP4 = reinterpret_cast<float4*>(sP);

        // chunk ids for this lane
        int  n[CH];
        bool v[CH];
        float4 acc[CH];
#pragma unroll
        for (int u = 0; u < CH; u++) {
            n[u] = half * (100 / SPLIT) + lane + 32 * u;
            v[u] = n[u] < half * (100 / SPLIT) + (100 / SPLIT) && n[u] < 100;
            acc[u] = v[u] ? identity4(n[u]) : make_float4(0.f, 0.f, 0.f, 0.f);
        }

        float coef = 1.0f;
#pragma unroll 3
        for (int jj = 0; jj < J; jj++) {
            coef *= f / (float)(jj + 1);
#pragma unroll
            for (int u = 0; u < CH; u++) {
                if (v[u]) {
                    float4 w = T4[jj * 100 + n[u]];
                    acc[u].x = fmaf(coef, w.x, acc[u].x);
                    acc[u].y = fmaf(coef, w.y, acc[u].y);
                    acc[u].z = fmaf(coef, w.z, acc[u].z);
                    acc[u].w = fmaf(coef, w.w, acc[u].w);
                }
            }
        }

        // write E to interleaved smem: chunk n = row i (=n/5), part r (=n%5)
#pragma unroll
        for (int u = 0; u < CH; u++) {
            if (v[u]) {
                const int i = n[u] / 5, r = n[u] - 5 * (n[u] / 5);
                sP4[i * NK4 + kk * 5 + r] = acc[u];
            }
        }
    } else {
        // stage sequence row (int4)
        const int st  = tid - LW * 32;
        const int nst = 256 - LW * 32;
        const int4* sq4 = reinterpret_cast<const int4*>(seq + (size_t)pb * L);
        int4* ss4 = reinterpret_cast<int4*>(sseq);
        for (int i = st; i < (L >> 2); i += nst) ss4[i] = __ldg(sq4 + i);
        for (int i = (L & ~3) + st; i < L; i += nst) sseq[i] = seq[(size_t)pb * L + i];
    }
    __syncthreads();

    // ---- rare cold path: squarings (one warp per matrix: wid < K, i.e. half==0) ----
    if (wid < K && sq_cnt > 0) {
        const int col = (lane < S) ? lane : 0;
        float a[S];
#pragma unroll
        for (int i = 0; i < S; i++) a[i] = sP[i * SROW + kk * S + col];
#pragma unroll 1
        for (int r = 0; r < sq_cnt; r++) {
            float c[S];
#pragma unroll
            for (int i = 0; i < S; i++) c[i] = 0.0f;
#pragma unroll
            for (int t = 0; t < S; t++) {
                const float av = a[t];
#pragma unroll
                for (int i = 0; i < S; i++) c[i] = fmaf(sP[i * SROW + kk * S + t], av, c[i]);
            }
            __syncwarp();
            if (lane < S) {
#pragma unroll
                for (int i = 0; i < S; i++) sP[i * SROW + kk * S + col] = c[i];
            }
            __syncwarp();
#pragma unroll
            for (int i = 0; i < S; i++) a[i] = c[i];
        }
    }
    __syncthreads();

    // ---- gather: out[pb,l,k,:] = P[seq[l]] row slice; fixed (dl,j) per lane ----
    if (lane < ACT) {
        const int dl = lane / NK4;
        const int j  = lane - dl * NK4;
        const float4* P4   = reinterpret_cast<const float4*>(sP);
        float4*       out4 = reinterpret_cast<float4*>(out) + (size_t)pb * (L * NK4);
        const int step = 8 * LPW;
#pragma unroll 2
        for (int l = wid * LPW + dl; l < L; l += step) {
            const int s0 = sseq[l];
            __stcs(&out4[l * NK4 + j], P4[s0 * NK4 + j]);
        }
    }
}

extern "C" void kernel_launch(void* const* d_in, const int* in_sizes, int n_in,
                              void* d_out, int out_size)
{
    const int*   seq  = (const int*)  d_in[0];
    const int*   ridx = (const int*)  d_in[1];
    const float* tauk = (const float*)d_in[2];
    const float* exch = (const float*)d_in[3];
    const float* eq   = (const float*)d_in[4];
    float*       out  = (float*)d_out;

    const int n_seq = in_sizes[0];
    const int n_ri  = in_sizes[1];
    const int n_tau = in_sizes[2];
    const int n_eq  = in_sizes[4];

    const int mk = n_eq / S;
    const int k  = out_size / (n_seq * S);
    const int m  = mk / k;
    const int b  = n_ri / m;
    const int L  = n_seq / n_ri;
    const int nr = n_tau / m;
    const int mb = m * b;

    setup_kernel<<<mk, 32 * J>>>(exch, eq);

    const int smem = k * SS * (int)sizeof(float) + L * (int)sizeof(int);
    switch (k) {
        case 1: main_kernel<1><<<mb, 256, smem>>>(seq, ridx, tauk, out, b, L, nr); break;
        case 2: main_kernel<2><<<mb, 256, smem>>>(seq, ridx, tauk, out, b, L, nr); break;
        case 3: main_kernel<3><<<mb, 256, smem>>>(seq, ridx, tauk, out, b, L, nr); break;
        case 4: main_kernel<4><<<mb, 256, smem>>>(seq, ridx, tauk, out, b, L, nr); break;
        default: break;
    }
}